// round 2
// baseline (speedup 1.0000x reference)
#include <cuda_runtime.h>
#include <math.h>

#define N_NODES 100000
#define N_EDGES 1600000
#define ETOT    (N_EDGES + N_NODES)
#define IN_DIM  256
#define HID     128
#define OUTD    64
#define NEG_SLOPE 0.2f
#define SCAN_NB ((N_NODES + 255) / 256)   // 391

// ---------------- scratch (static device globals; no allocation) ----------------
static __device__ __align__(128) float g_h1[(size_t)N_NODES * HID];   // x@W1
static __device__ __align__(128) float g_o1[(size_t)N_NODES * HID];   // elu(agg1 + b1)
static __device__ __align__(128) float g_h2[(size_t)N_NODES * OUTD];  // o1@W2
static __device__ float g_ssrc[N_NODES];
static __device__ float g_sdst[N_NODES];
static __device__ int   g_cnt[N_NODES];
static __device__ int   g_cur[N_NODES];
static __device__ int   g_off[N_NODES + 1];
static __device__ int   g_bsum[512];
static __device__ int   g_col[ETOT];
static __device__ int   g_slot[ETOT];
static __device__ float g_eval[ETOT];

// ---------------- CSR build ----------------
__global__ void k_zero() {
    int i = blockIdx.x * blockDim.x + threadIdx.x;
    if (i < N_NODES) { g_cnt[i] = 0; g_cur[i] = 0; }
}

__global__ void k_count(const int* __restrict__ ei) {
    int t = blockIdx.x * blockDim.x + threadIdx.x;
    if (t >= ETOT) return;
    int dst = (t < N_EDGES) ? ei[N_EDGES + t] : (t - N_EDGES);
    atomicAdd(&g_cnt[dst], 1);
}

__global__ void k_scan1() {
    __shared__ int s[256];
    int t = threadIdx.x, idx = blockIdx.x * 256 + t;
    int v = (idx < N_NODES) ? g_cnt[idx] : 0;
    s[t] = v; __syncthreads();
    #pragma unroll
    for (int o = 1; o < 256; o <<= 1) {
        int u = (t >= o) ? s[t - o] : 0;
        __syncthreads();
        s[t] += u;
        __syncthreads();
    }
    if (idx < N_NODES) g_off[idx] = s[t] - v;   // exclusive within block
    if (t == 255) g_bsum[blockIdx.x] = s[t];
}

__global__ void k_scan2(int nb) {
    __shared__ int s[512];
    int t = threadIdx.x;
    int v = (t < nb) ? g_bsum[t] : 0;
    s[t] = v; __syncthreads();
    #pragma unroll
    for (int o = 1; o < 512; o <<= 1) {
        int u = (t >= o) ? s[t - o] : 0;
        __syncthreads();
        s[t] += u;
        __syncthreads();
    }
    g_bsum[t] = s[t] - v;                       // exclusive block offsets
}

__global__ void k_scan3() {
    int t = threadIdx.x, idx = blockIdx.x * 256 + t;
    if (idx < N_NODES) g_off[idx] += g_bsum[blockIdx.x];
    if (idx == 0) g_off[N_NODES] = ETOT;
}

// ---------------- GEMM v2: C[M,NCOL] = A[M,K] @ W[K,NCOL], fp32 ----------------
// BM=128, BK=16, 256 threads in 16x16 grid, per-thread 8 x (NCOL/16) register tile.
// A transposed into smem (conflict-free float4 reads); all smem reads are float4.
template<int K, int NCOL>
__global__ void k_gemm(const float* __restrict__ A, const float* __restrict__ W,
                       float* __restrict__ C, int M) {
    constexpr int BM = 128, BK = 16;
    constexpr int TN = NCOL / 16;            // 8 (HID) or 4 (OUTD)
    constexpr int AS_LD = BM + 4;            // 132 (keeps float4 alignment: 528B rows)
    constexpr int NC4 = NCOL / 4;
    __shared__ float As[BK][AS_LD];
    __shared__ float Ws[BK][NCOL];
    const int tid = threadIdx.x;
    const int tx = tid & 15;                 // col group
    const int ty = tid >> 4;                 // row group
    const int m0 = blockIdx.x * BM;

    float acc[8][TN];
    #pragma unroll
    for (int r = 0; r < 8; r++)
        #pragma unroll
        for (int n = 0; n < TN; n++) acc[r][n] = 0.f;

    for (int k0 = 0; k0 < K; k0 += BK) {
        // Load A tile, transpose into As[k][m]
        #pragma unroll
        for (int i = tid; i < BM * 4; i += 256) {
            int row = i >> 2, kf = (i & 3) * 4;
            float4 v = make_float4(0.f, 0.f, 0.f, 0.f);
            int gr = m0 + row;
            if (gr < M) v = *(const float4*)(A + (size_t)gr * K + k0 + kf);
            As[kf + 0][row] = v.x;
            As[kf + 1][row] = v.y;
            As[kf + 2][row] = v.z;
            As[kf + 3][row] = v.w;
        }
        // Load W tile
        #pragma unroll
        for (int i = tid; i < BK * NC4; i += 256) {
            int wr = i / NC4, wc = (i % NC4) * 4;
            *(float4*)&Ws[wr][wc] = *(const float4*)(W + (size_t)(k0 + wr) * NCOL + wc);
        }
        __syncthreads();
        #pragma unroll
        for (int kk = 0; kk < BK; kk++) {
            float4 a0 = *(const float4*)&As[kk][ty * 8];
            float4 a1 = *(const float4*)&As[kk][ty * 8 + 4];
            float a_[8] = {a0.x, a0.y, a0.z, a0.w, a1.x, a1.y, a1.z, a1.w};
            float w_[TN];
            #pragma unroll
            for (int n = 0; n < TN; n += 4) {
                float4 wv = *(const float4*)&Ws[kk][tx * TN + n];
                w_[n] = wv.x; w_[n + 1] = wv.y; w_[n + 2] = wv.z; w_[n + 3] = wv.w;
            }
            #pragma unroll
            for (int r = 0; r < 8; r++)
                #pragma unroll
                for (int n = 0; n < TN; n++)
                    acc[r][n] = fmaf(a_[r], w_[n], acc[r][n]);
        }
        __syncthreads();
    }

    #pragma unroll
    for (int r = 0; r < 8; r++) {
        int row = m0 + ty * 8 + r;
        if (row < M) {
            #pragma unroll
            for (int n = 0; n < TN; n += 4) {
                float4 v = make_float4(acc[r][n], acc[r][n + 1], acc[r][n + 2], acc[r][n + 3]);
                *(float4*)(C + (size_t)row * NCOL + tx * TN + n) = v;
            }
        }
    }
}

// ---------------- per-node attention scores s_src, s_dst ----------------
template<int F>
__global__ void k_sdot(const float* __restrict__ h, const float* __restrict__ asrc,
                       const float* __restrict__ adst) {
    int node = (blockIdx.x * blockDim.x + threadIdx.x) >> 5;
    if (node >= N_NODES) return;
    int lane = threadIdx.x & 31;
    float d1 = 0.f, d2 = 0.f;
    if (F == 128) {
        float4 hv = *(const float4*)(h + (size_t)node * 128 + lane * 4);
        float4 a1 = *(const float4*)(asrc + lane * 4);
        float4 a2 = *(const float4*)(adst + lane * 4);
        d1 = hv.x * a1.x + hv.y * a1.y + hv.z * a1.z + hv.w * a1.w;
        d2 = hv.x * a2.x + hv.y * a2.y + hv.z * a2.z + hv.w * a2.w;
    } else {
        float2 hv = *(const float2*)(h + (size_t)node * 64 + lane * 2);
        float2 a1 = *(const float2*)(asrc + lane * 2);
        float2 a2 = *(const float2*)(adst + lane * 2);
        d1 = hv.x * a1.x + hv.y * a1.y;
        d2 = hv.x * a2.x + hv.y * a2.y;
    }
    #pragma unroll
    for (int o = 16; o; o >>= 1) {
        d1 += __shfl_xor_sync(0xffffffffu, d1, o);
        d2 += __shfl_xor_sync(0xffffffffu, d2, o);
    }
    if (lane == 0) { g_ssrc[node] = d1; g_sdst[node] = d2; }
}

// ---------------- edge score kernels ----------------
__device__ __forceinline__ void edge_decode(const int* __restrict__ ei, int t,
                                            int& src, int& dst) {
    if (t < N_EDGES) { src = ei[t]; dst = ei[N_EDGES + t]; }
    else             { src = dst = t - N_EDGES; }
}

// Layer 1: compute e, assign CSR slot, record slot for layer 2 reuse.
__global__ void k_scatter1(const int* __restrict__ ei) {
    int t = blockIdx.x * blockDim.x + threadIdx.x;
    if (t >= ETOT) return;
    int src, dst; edge_decode(ei, t, src, dst);
    float e = g_ssrc[src] + g_sdst[dst];
    e = (e > 0.f) ? e : NEG_SLOPE * e;
    int pos = g_off[dst] + atomicAdd(&g_cur[dst], 1);
    g_col[pos] = src;
    g_eval[pos] = e;
    g_slot[t] = pos;
}

// Layer 2: CSR structure fixed; just refresh eval via recorded slots.
__global__ void k_eval2(const int* __restrict__ ei) {
    int t = blockIdx.x * blockDim.x + threadIdx.x;
    if (t >= ETOT) return;
    int src, dst; edge_decode(ei, t, src, dst);
    float e = g_ssrc[src] + g_sdst[dst];
    e = (e > 0.f) ? e : NEG_SLOPE * e;
    g_eval[g_slot[t]] = e;
}

// ---------------- warp-per-dst softmax aggregation v2 ----------------
// Chunk 32 edges: one expf + one col load per lane, shfl-broadcast, 4-wide
// unrolled gather loop for MLP=4.
#define FULLM 0xffffffffu

template<bool ELU>
__global__ void k_agg128(const float* __restrict__ h, const float* __restrict__ bias,
                         float* __restrict__ out) {
    int node = (blockIdx.x * blockDim.x + threadIdx.x) >> 5;
    if (node >= N_NODES) return;
    int lane = threadIdx.x & 31;
    int beg = g_off[node], end = g_off[node + 1];

    float m = -1e30f;
    for (int j = beg + lane; j < end; j += 32) m = fmaxf(m, g_eval[j]);
    #pragma unroll
    for (int o = 16; o; o >>= 1) m = fmaxf(m, __shfl_xor_sync(FULLM, m, o));

    float s = 0.f;
    for (int j = beg + lane; j < end; j += 32) s += __expf(g_eval[j] - m);
    #pragma unroll
    for (int o = 16; o; o >>= 1) s += __shfl_xor_sync(FULLM, s, o);
    float inv = 1.f / s;

    float4 acc = make_float4(0.f, 0.f, 0.f, 0.f);
    for (int c0 = beg; c0 < end; c0 += 32) {
        int n = min(32, end - c0);
        float aw = 0.f; int cs = 0;
        if (lane < n) {
            aw = __expf(g_eval[c0 + lane] - m) * inv;
            cs = g_col[c0 + lane];
        }
        int k = 0;
        for (; k + 4 <= n; k += 4) {
            float a0 = __shfl_sync(FULLM, aw, k);
            float a1 = __shfl_sync(FULLM, aw, k + 1);
            float a2 = __shfl_sync(FULLM, aw, k + 2);
            float a3 = __shfl_sync(FULLM, aw, k + 3);
            int s0 = __shfl_sync(FULLM, cs, k);
            int s1 = __shfl_sync(FULLM, cs, k + 1);
            int s2 = __shfl_sync(FULLM, cs, k + 2);
            int s3 = __shfl_sync(FULLM, cs, k + 3);
            float4 v0 = *(const float4*)(h + (size_t)s0 * 128 + lane * 4);
            float4 v1 = *(const float4*)(h + (size_t)s1 * 128 + lane * 4);
            float4 v2 = *(const float4*)(h + (size_t)s2 * 128 + lane * 4);
            float4 v3 = *(const float4*)(h + (size_t)s3 * 128 + lane * 4);
            acc.x = fmaf(a0, v0.x, acc.x); acc.y = fmaf(a0, v0.y, acc.y);
            acc.z = fmaf(a0, v0.z, acc.z); acc.w = fmaf(a0, v0.w, acc.w);
            acc.x = fmaf(a1, v1.x, acc.x); acc.y = fmaf(a1, v1.y, acc.y);
            acc.z = fmaf(a1, v1.z, acc.z); acc.w = fmaf(a1, v1.w, acc.w);
            acc.x = fmaf(a2, v2.x, acc.x); acc.y = fmaf(a2, v2.y, acc.y);
            acc.z = fmaf(a2, v2.z, acc.z); acc.w = fmaf(a2, v2.w, acc.w);
            acc.x = fmaf(a3, v3.x, acc.x); acc.y = fmaf(a3, v3.y, acc.y);
            acc.z = fmaf(a3, v3.z, acc.z); acc.w = fmaf(a3, v3.w, acc.w);
        }
        for (; k < n; k++) {
            float a0 = __shfl_sync(FULLM, aw, k);
            int s0 = __shfl_sync(FULLM, cs, k);
            float4 v0 = *(const float4*)(h + (size_t)s0 * 128 + lane * 4);
            acc.x = fmaf(a0, v0.x, acc.x); acc.y = fmaf(a0, v0.y, acc.y);
            acc.z = fmaf(a0, v0.z, acc.z); acc.w = fmaf(a0, v0.w, acc.w);
        }
    }
    float4 bv = *(const float4*)(bias + lane * 4);
    acc.x += bv.x; acc.y += bv.y; acc.z += bv.z; acc.w += bv.w;
    if (ELU) {
        acc.x = (acc.x > 0.f) ? acc.x : expm1f(acc.x);
        acc.y = (acc.y > 0.f) ? acc.y : expm1f(acc.y);
        acc.z = (acc.z > 0.f) ? acc.z : expm1f(acc.z);
        acc.w = (acc.w > 0.f) ? acc.w : expm1f(acc.w);
    }
    *(float4*)(out + (size_t)node * 128 + lane * 4) = acc;
}

__global__ void k_agg64(const float* __restrict__ h, const float* __restrict__ bias,
                        float* __restrict__ out) {
    int node = (blockIdx.x * blockDim.x + threadIdx.x) >> 5;
    if (node >= N_NODES) return;
    int lane = threadIdx.x & 31;
    int beg = g_off[node], end = g_off[node + 1];

    float m = -1e30f;
    for (int j = beg + lane; j < end; j += 32) m = fmaxf(m, g_eval[j]);
    #pragma unroll
    for (int o = 16; o; o >>= 1) m = fmaxf(m, __shfl_xor_sync(FULLM, m, o));

    float s = 0.f;
    for (int j = beg + lane; j < end; j += 32) s += __expf(g_eval[j] - m);
    #pragma unroll
    for (int o = 16; o; o >>= 1) s += __shfl_xor_sync(FULLM, s, o);
    float inv = 1.f / s;

    float2 acc = make_float2(0.f, 0.f);
    for (int c0 = beg; c0 < end; c0 += 32) {
        int n = min(32, end - c0);
        float aw = 0.f; int cs = 0;
        if (lane < n) {
            aw = __expf(g_eval[c0 + lane] - m) * inv;
            cs = g_col[c0 + lane];
        }
        int k = 0;
        for (; k + 4 <= n; k += 4) {
            float a0 = __shfl_sync(FULLM, aw, k);
            float a1 = __shfl_sync(FULLM, aw, k + 1);
            float a2 = __shfl_sync(FULLM, aw, k + 2);
            float a3 = __shfl_sync(FULLM, aw, k + 3);
            int s0 = __shfl_sync(FULLM, cs, k);
            int s1 = __shfl_sync(FULLM, cs, k + 1);
            int s2 = __shfl_sync(FULLM, cs, k + 2);
            int s3 = __shfl_sync(FULLM, cs, k + 3);
            float2 v0 = *(const float2*)(h + (size_t)s0 * 64 + lane * 2);
            float2 v1 = *(const float2*)(h + (size_t)s1 * 64 + lane * 2);
            float2 v2 = *(const float2*)(h + (size_t)s2 * 64 + lane * 2);
            float2 v3 = *(const float2*)(h + (size_t)s3 * 64 + lane * 2);
            acc.x = fmaf(a0, v0.x, acc.x); acc.y = fmaf(a0, v0.y, acc.y);
            acc.x = fmaf(a1, v1.x, acc.x); acc.y = fmaf(a1, v1.y, acc.y);
            acc.x = fmaf(a2, v2.x, acc.x); acc.y = fmaf(a2, v2.y, acc.y);
            acc.x = fmaf(a3, v3.x, acc.x); acc.y = fmaf(a3, v3.y, acc.y);
        }
        for (; k < n; k++) {
            float a0 = __shfl_sync(FULLM, aw, k);
            int s0 = __shfl_sync(FULLM, cs, k);
            float2 v0 = *(const float2*)(h + (size_t)s0 * 64 + lane * 2);
            acc.x = fmaf(a0, v0.x, acc.x); acc.y = fmaf(a0, v0.y, acc.y);
        }
    }
    float2 bv = *(const float2*)(bias + lane * 2);
    acc.x += bv.x; acc.y += bv.y;
    *(float2*)(out + (size_t)node * 64 + lane * 2) = acc;
}

// ---------------- launch ----------------
extern "C" void kernel_launch(void* const* d_in, const int* in_sizes, int n_in,
                              void* d_out, int out_size) {
    const float* x     = (const float*)d_in[0];
    const int*   ei    = (const int*)d_in[1];
    const float* W1    = (const float*)d_in[2];
    const float* a1s   = (const float*)d_in[3];
    const float* a1d   = (const float*)d_in[4];
    const float* b1    = (const float*)d_in[5];
    const float* W2    = (const float*)d_in[6];
    const float* a2s   = (const float*)d_in[7];
    const float* a2d   = (const float*)d_in[8];
    const float* b2    = (const float*)d_in[9];
    float* out = (float*)d_out;

    const int nodeBlk  = (N_NODES + 255) / 256;
    const int edgeBlk  = (ETOT + 255) / 256;
    const int warpBlk  = (N_NODES * 32 + 255) / 256;   // warp-per-node kernels
    const int gemmBlk  = (N_NODES + 127) / 128;

    // CSR build interleaved with layer-1 GEMM (gemm placed at the profiled slot)
    k_zero<<<nodeBlk, 256>>>();
    k_count<<<edgeBlk, 256>>>(ei);
    k_scan1<<<SCAN_NB, 256>>>();
    k_gemm<IN_DIM, HID><<<gemmBlk, 256>>>(x, W1, g_h1, N_NODES);
    k_scan2<<<1, 512>>>(SCAN_NB);
    k_sdot<HID><<<warpBlk, 256>>>(g_h1, a1s, a1d);
    k_scan3<<<SCAN_NB, 256>>>();
    k_scatter1<<<edgeBlk, 256>>>(ei);
    k_agg128<true><<<warpBlk, 256>>>(g_h1, b1, g_o1);

    // Layer 2
    k_gemm<HID, OUTD><<<gemmBlk, 256>>>(g_o1, W2, g_h2, N_NODES);
    k_sdot<OUTD><<<warpBlk, 256>>>(g_h2, a2s, a2d);
    k_eval2<<<edgeBlk, 256>>>(ei);
    k_agg64<<<warpBlk, 256>>>(g_h2, b2, out);
}

// round 3
// speedup vs baseline: 1.0387x; 1.0387x over previous
#include <cuda_runtime.h>
#include <math.h>
#include <float.h>

#define N_NODES 100000
#define N_EDGES 1600000
#define ETOT    (N_EDGES + N_NODES)
#define IN_DIM  256
#define HID     128
#define OUTD    64
#define NEG_SLOPE 0.2f
#define SCAN_NB ((N_NODES + 255) / 256)   // 391
#define FULLM 0xffffffffu

// ---------------- scratch (static device globals; no allocation) ----------------
static __device__ __align__(128) float g_h1[(size_t)N_NODES * HID];   // x@W1
static __device__ __align__(128) float g_o1[(size_t)N_NODES * HID];   // elu(agg1 + b1)
static __device__ __align__(128) float g_h2[(size_t)N_NODES * OUTD];  // o1@W2
static __device__ float g_ssrc[N_NODES];
static __device__ float g_sdst[N_NODES];
static __device__ int   g_cnt[N_NODES];
static __device__ int   g_cur[N_NODES];
static __device__ int   g_off[N_NODES + 1];
static __device__ int   g_bsum[512];
static __device__ int   g_col[ETOT];

// ---------------- CSR build ----------------
__global__ void k_zeroA() {
    int i = blockIdx.x * blockDim.x + threadIdx.x;
    if (i < N_NODES) g_cnt[i] = 0;
}
__global__ void k_zeroB() {
    int i = blockIdx.x * blockDim.x + threadIdx.x;
    if (i < N_NODES) g_cur[i] = 0;
}

__global__ void k_count(const int* __restrict__ ei) {
    int t = blockIdx.x * blockDim.x + threadIdx.x;
    if (t >= ETOT) return;
    int dst = (t < N_EDGES) ? ei[N_EDGES + t] : (t - N_EDGES);
    atomicAdd(&g_cnt[dst], 1);
}

__global__ void k_scan1() {
    __shared__ int s[256];
    int t = threadIdx.x, idx = blockIdx.x * 256 + t;
    int v = (idx < N_NODES) ? g_cnt[idx] : 0;
    s[t] = v; __syncthreads();
    #pragma unroll
    for (int o = 1; o < 256; o <<= 1) {
        int u = (t >= o) ? s[t - o] : 0;
        __syncthreads();
        s[t] += u;
        __syncthreads();
    }
    if (idx < N_NODES) g_off[idx] = s[t] - v;
    if (t == 255) g_bsum[blockIdx.x] = s[t];
}

__global__ void k_scan2(int nb) {
    __shared__ int s[512];
    int t = threadIdx.x;
    int v = (t < nb) ? g_bsum[t] : 0;
    s[t] = v; __syncthreads();
    #pragma unroll
    for (int o = 1; o < 512; o <<= 1) {
        int u = (t >= o) ? s[t - o] : 0;
        __syncthreads();
        s[t] += u;
        __syncthreads();
    }
    g_bsum[t] = s[t] - v;
}

__global__ void k_scan3() {
    int t = threadIdx.x, idx = blockIdx.x * 256 + t;
    if (idx < N_NODES) g_off[idx] += g_bsum[blockIdx.x];
    if (idx == 0) g_off[N_NODES] = ETOT;
}

// CSR column fill (structure only; no edge scores needed anymore)
__global__ void k_fill(const int* __restrict__ ei) {
    int t = blockIdx.x * blockDim.x + threadIdx.x;
    if (t >= ETOT) return;
    int src, dst;
    if (t < N_EDGES) { src = ei[t]; dst = ei[N_EDGES + t]; }
    else             { src = dst = t - N_EDGES; }
    int pos = g_off[dst] + atomicAdd(&g_cur[dst], 1);
    g_col[pos] = src;
}

// ---------------- GEMM v3 + fused attention-score epilogue ----------------
// C[M,NCOL] = A[M,K] @ W[K,NCOL]; also ssrc[row]=C[row]@asrc, sdst[row]=C[row]@adst.
// TM=8 rows x TN=4 cols per thread; 256 threads = (NCOL/4) x (BM/8).
// As stored transposed (warp-broadcast reads), Ws float4 conflict-free.
template<int K, int NCOL, int BM>
__global__ void k_gemm(const float* __restrict__ A, const float* __restrict__ W,
                       float* __restrict__ C,
                       const float* __restrict__ asrc, const float* __restrict__ adst,
                       float* __restrict__ ssrc, float* __restrict__ sdst, int M) {
    constexpr int TN = 4, TM = 8, BK = 16;
    constexpr int TX = NCOL / TN;          // 32 (HID) or 16 (OUTD)
    constexpr int ALD = BM + 4;            // pad keeps 16B alignment (BM%4==0)
    constexpr int NC4 = NCOL / 4;
    __shared__ float As[BK][ALD];
    __shared__ float Ws[BK][NCOL];
    const int tid = threadIdx.x;
    const int tx = tid % TX;
    const int ty = tid / TX;
    const int m0 = blockIdx.x * BM;

    float acc[TM][TN];
    #pragma unroll
    for (int r = 0; r < TM; r++)
        #pragma unroll
        for (int n = 0; n < TN; n++) acc[r][n] = 0.f;

    for (int k0 = 0; k0 < K; k0 += BK) {
        #pragma unroll
        for (int i = tid; i < BM * 4; i += 256) {
            int row = i >> 2, kf = (i & 3) * 4;
            float4 v = make_float4(0.f, 0.f, 0.f, 0.f);
            int gr = m0 + row;
            if (gr < M) v = *(const float4*)(A + (size_t)gr * K + k0 + kf);
            As[kf + 0][row] = v.x;
            As[kf + 1][row] = v.y;
            As[kf + 2][row] = v.z;
            As[kf + 3][row] = v.w;
        }
        #pragma unroll
        for (int i = tid; i < BK * NC4; i += 256) {
            int wr = i / NC4, wc = (i % NC4) * 4;
            *(float4*)&Ws[wr][wc] = *(const float4*)(W + (size_t)(k0 + wr) * NCOL + wc);
        }
        __syncthreads();
        #pragma unroll
        for (int kk = 0; kk < BK; kk++) {
            float4 a0 = *(const float4*)&As[kk][ty * TM];
            float4 a1 = *(const float4*)&As[kk][ty * TM + 4];
            float4 wv = *(const float4*)&Ws[kk][tx * TN];
            float a_[TM] = {a0.x, a0.y, a0.z, a0.w, a1.x, a1.y, a1.z, a1.w};
            float w_[TN] = {wv.x, wv.y, wv.z, wv.w};
            #pragma unroll
            for (int r = 0; r < TM; r++)
                #pragma unroll
                for (int n = 0; n < TN; n++)
                    acc[r][n] = fmaf(a_[r], w_[n], acc[r][n]);
        }
        __syncthreads();
    }

    // store C
    #pragma unroll
    for (int r = 0; r < TM; r++) {
        int row = m0 + ty * TM + r;
        if (row < M) {
            float4 v = make_float4(acc[r][0], acc[r][1], acc[r][2], acc[r][3]);
            *(float4*)(C + (size_t)row * NCOL + tx * TN) = v;
        }
    }

    // fused attention scores: per-thread partials over TN cols, reduce over tx group
    float4 a1v = *(const float4*)(asrc + tx * TN);
    float4 a2v = *(const float4*)(adst + tx * TN);
    float p1[TM], p2[TM];
    #pragma unroll
    for (int r = 0; r < TM; r++) {
        p1[r] = acc[r][0] * a1v.x + acc[r][1] * a1v.y + acc[r][2] * a1v.z + acc[r][3] * a1v.w;
        p2[r] = acc[r][0] * a2v.x + acc[r][1] * a2v.y + acc[r][2] * a2v.z + acc[r][3] * a2v.w;
    }
    #pragma unroll
    for (int o = TX / 2; o; o >>= 1) {
        #pragma unroll
        for (int r = 0; r < TM; r++) {
            p1[r] += __shfl_xor_sync(FULLM, p1[r], o);
            p2[r] += __shfl_xor_sync(FULLM, p2[r], o);
        }
    }
    if (tx == 0) {
        #pragma unroll
        for (int r = 0; r < TM; r++) {
            int row = m0 + ty * TM + r;
            if (row < M) { ssrc[row] = p1[r]; sdst[row] = p2[r]; }
        }
    }
}

// ---------------- online-softmax warp-per-dst aggregation ----------------
// Single pass over incoming edges: e computed on the fly from ssrc/sdst,
// flash-style running (max, sum, acc) with rescaling.
template<int F, bool ELU>   // F = 128 or 64; VEC = F/32 floats per lane
__global__ void k_agg(const float* __restrict__ h,
                      const float* __restrict__ ssrc, const float* __restrict__ sdst,
                      const float* __restrict__ bias, float* __restrict__ out) {
    constexpr int VEC = F / 32;            // 4 or 2
    int node = (blockIdx.x * blockDim.x + threadIdx.x) >> 5;
    if (node >= N_NODES) return;
    int lane = threadIdx.x & 31;
    int beg = g_off[node], end = g_off[node + 1];
    float sd = sdst[node];

    float m = -FLT_MAX, s = 0.f;
    float acc[VEC];
    #pragma unroll
    for (int v = 0; v < VEC; v++) acc[v] = 0.f;

    for (int c0 = beg; c0 < end; c0 += 32) {
        int n = min(32, end - c0);
        float e = -FLT_MAX; int cs = 0;
        if (lane < n) {
            cs = g_col[c0 + lane];
            float t = ssrc[cs] + sd;
            e = (t > 0.f) ? t : NEG_SLOPE * t;
        }
        float cm = e;
        #pragma unroll
        for (int o = 16; o; o >>= 1) cm = fmaxf(cm, __shfl_xor_sync(FULLM, cm, o));
        float mn = fmaxf(m, cm);
        float scale = __expf(m - mn);      // first iter: expf(-inf)=0
        s *= scale;
        #pragma unroll
        for (int v = 0; v < VEC; v++) acc[v] *= scale;

        float w = (lane < n) ? __expf(e - mn) : 0.f;
        float ws = w;
        #pragma unroll
        for (int o = 16; o; o >>= 1) ws += __shfl_xor_sync(FULLM, ws, o);
        s += ws;
        m = mn;

        int k = 0;
        for (; k + 4 <= n; k += 4) {
            float w0 = __shfl_sync(FULLM, w, k);
            float w1 = __shfl_sync(FULLM, w, k + 1);
            float w2 = __shfl_sync(FULLM, w, k + 2);
            float w3 = __shfl_sync(FULLM, w, k + 3);
            int s0 = __shfl_sync(FULLM, cs, k);
            int s1 = __shfl_sync(FULLM, cs, k + 1);
            int s2 = __shfl_sync(FULLM, cs, k + 2);
            int s3 = __shfl_sync(FULLM, cs, k + 3);
            const float* p0 = h + (size_t)s0 * F + lane * VEC;
            const float* p1 = h + (size_t)s1 * F + lane * VEC;
            const float* p2 = h + (size_t)s2 * F + lane * VEC;
            const float* p3 = h + (size_t)s3 * F + lane * VEC;
            if (VEC == 4) {
                float4 v0 = *(const float4*)p0;
                float4 v1 = *(const float4*)p1;
                float4 v2 = *(const float4*)p2;
                float4 v3 = *(const float4*)p3;
                acc[0] = fmaf(w0, v0.x, acc[0]); acc[1] = fmaf(w0, v0.y, acc[1]);
                acc[2] = fmaf(w0, v0.z, acc[2]); acc[3] = fmaf(w0, v0.w, acc[3]);
                acc[0] = fmaf(w1, v1.x, acc[0]); acc[1] = fmaf(w1, v1.y, acc[1]);
                acc[2] = fmaf(w1, v1.z, acc[2]); acc[3] = fmaf(w1, v1.w, acc[3]);
                acc[0] = fmaf(w2, v2.x, acc[0]); acc[1] = fmaf(w2, v2.y, acc[1]);
                acc[2] = fmaf(w2, v2.z, acc[2]); acc[3] = fmaf(w2, v2.w, acc[3]);
                acc[0] = fmaf(w3, v3.x, acc[0]); acc[1] = fmaf(w3, v3.y, acc[1]);
                acc[2] = fmaf(w3, v3.z, acc[2]); acc[3] = fmaf(w3, v3.w, acc[3]);
            } else {
                float2 v0 = *(const float2*)p0;
                float2 v1 = *(const float2*)p1;
                float2 v2 = *(const float2*)p2;
                float2 v3 = *(const float2*)p3;
                acc[0] = fmaf(w0, v0.x, acc[0]); acc[1] = fmaf(w0, v0.y, acc[1]);
                acc[0] = fmaf(w1, v1.x, acc[0]); acc[1] = fmaf(w1, v1.y, acc[1]);
                acc[0] = fmaf(w2, v2.x, acc[0]); acc[1] = fmaf(w2, v2.y, acc[1]);
                acc[0] = fmaf(w3, v3.x, acc[0]); acc[1] = fmaf(w3, v3.y, acc[1]);
            }
        }
        for (; k < n; k++) {
            float w0 = __shfl_sync(FULLM, w, k);
            int s0 = __shfl_sync(FULLM, cs, k);
            const float* p0 = h + (size_t)s0 * F + lane * VEC;
            if (VEC == 4) {
                float4 v0 = *(const float4*)p0;
                acc[0] = fmaf(w0, v0.x, acc[0]); acc[1] = fmaf(w0, v0.y, acc[1]);
                acc[2] = fmaf(w0, v0.z, acc[2]); acc[3] = fmaf(w0, v0.w, acc[3]);
            } else {
                float2 v0 = *(const float2*)p0;
                acc[0] = fmaf(w0, v0.x, acc[0]); acc[1] = fmaf(w0, v0.y, acc[1]);
            }
        }
    }

    float inv = 1.f / s;
    #pragma unroll
    for (int v = 0; v < VEC; v++) {
        float bv = bias[lane * VEC + v];
        float r = acc[v] * inv + bv;
        if (ELU) r = (r > 0.f) ? r : expm1f(r);
        acc[v] = r;
    }
    if (VEC == 4) {
        float4 o4 = make_float4(acc[0], acc[1], acc[2], acc[3]);
        *(float4*)(out + (size_t)node * F + lane * 4) = o4;
    } else {
        float2 o2 = make_float2(acc[0], acc[1]);
        *(float2*)(out + (size_t)node * F + lane * 2) = o2;
    }
}

// ---------------- launch ----------------
extern "C" void kernel_launch(void* const* d_in, const int* in_sizes, int n_in,
                              void* d_out, int out_size) {
    const float* x   = (const float*)d_in[0];
    const int*   ei  = (const int*)d_in[1];
    const float* W1  = (const float*)d_in[2];
    const float* a1s = (const float*)d_in[3];
    const float* a1d = (const float*)d_in[4];
    const float* b1  = (const float*)d_in[5];
    const float* W2  = (const float*)d_in[6];
    const float* a2s = (const float*)d_in[7];
    const float* a2d = (const float*)d_in[8];
    const float* b2  = (const float*)d_in[9];
    float* out = (float*)d_out;

    const int nodeBlk = (N_NODES + 255) / 256;
    const int edgeBlk = (ETOT + 255) / 256;
    const int warpBlk = (N_NODES * 32 + 255) / 256;
    const int g1Blk   = (N_NODES + 63) / 64;     // BM=64
    const int g2Blk   = (N_NODES + 127) / 128;   // BM=128

    // Launch order chosen so index 3 (the ncu-profiled launch) is k_count,
    // probing the edge-atomic throughput hypothesis.
    k_zeroA<<<nodeBlk, 256>>>();                                             // 0
    k_gemm<IN_DIM, HID, 64><<<g1Blk, 256>>>(x, W1, g_h1, a1s, a1d,
                                            g_ssrc, g_sdst, N_NODES);        // 1
    k_zeroB<<<nodeBlk, 256>>>();                                             // 2
    k_count<<<edgeBlk, 256>>>(ei);                                           // 3  <- profiled
    k_scan1<<<SCAN_NB, 256>>>();                                             // 4
    k_scan2<<<1, 512>>>(SCAN_NB);                                            // 5
    k_scan3<<<SCAN_NB, 256>>>();                                             // 6
    k_fill<<<edgeBlk, 256>>>(ei);                                            // 7
    k_agg<HID, true><<<warpBlk, 256>>>(g_h1, g_ssrc, g_sdst, b1, g_o1);      // 8
    k_gemm<HID, OUTD, 128><<<g2Blk, 256>>>(g_o1, W2, g_h2, a2s, a2d,
                                           g_ssrc, g_sdst, N_NODES);         // 9
    k_agg<OUTD, false><<<warpBlk, 256>>>(g_h2, g_ssrc, g_sdst, b2, out);     // 10
}